// round 1
// baseline (speedup 1.0000x reference)
#include <cuda_runtime.h>

#define NN 50000
#define EE 800000
#define RR 3
#define DD 128
#define HH 4

// ---------------- scratch (device globals; no allocation allowed) -------------
__device__ float g_h[(size_t)RR * NN * DD];     // per-relation transformed features
__device__ float g_asrc[RR * NN * HH];
__device__ float g_adst[RR * NN * HH];
__device__ float g_denom[RR * NN * HH];
__device__ float g_acc[(size_t)NN * DD];        // fused output accumulator
__device__ float g_gw[RR];
__device__ float g_biasf[DD];

// ---------------- packed fp32x2 helpers ---------------------------------------
#define PACK_DUP(d, f) asm("mov.b64 %0, {%1, %2};" : "=l"(d) : "f"(f), "f"(f))
#define FMA2(d, a, b, c) \
    asm("fma.rn.f32x2 %0, %1, %2, %3;" : "=l"(d) : "l"(a), "l"(b), "l"(c))

// ---------------- K0: gate softmax + fused bias --------------------------------
__global__ void k_prep(const float* __restrict__ gate,
                       const float* __restrict__ bias,
                       float* __restrict__ out_gw) {
    __shared__ float gw[RR];
    int d = threadIdx.x;  // 128 threads
    if (d == 0) {
        float m = gate[0];
        for (int r = 1; r < RR; r++) m = fmaxf(m, gate[r]);
        float e[RR], s = 0.f;
        for (int r = 0; r < RR; r++) { e[r] = expf(gate[r] - m); s += e[r]; }
        for (int r = 0; r < RR; r++) {
            gw[r] = e[r] / s;
            g_gw[r] = gw[r];
            out_gw[r] = gw[r];
        }
    }
    __syncthreads();
    float b = 0.f;
    for (int r = 0; r < RR; r++) b += gw[r] * bias[r * DD + d];
    g_biasf[d] = b;
}

// ---------------- K1: init acc = x + fused_bias ; zero denom -------------------
__global__ void k_init(const float* __restrict__ x) {
    int i = blockIdx.x * blockDim.x + threadIdx.x;
    const int ACC4 = NN * DD / 4;           // 1,600,000
    const int DEN4 = RR * NN * HH / 4;      // 150,000
    if (i < ACC4) {
        float4 xv = ((const float4*)x)[i];
        int d4 = (i & 31) * 4;              // DD/4 == 32
        float4 bf = *(const float4*)&g_biasf[d4];
        float4 o;
        o.x = xv.x + bf.x; o.y = xv.y + bf.y;
        o.z = xv.z + bf.z; o.w = xv.w + bf.w;
        ((float4*)g_acc)[i] = o;
    } else {
        int j = i - ACC4;
        if (j < DEN4) ((float4*)g_denom)[j] = make_float4(0.f, 0.f, 0.f, 0.f);
    }
}

// ---------------- K2: GEMM h_r = x @ W_r  (fp32x2 packed FFMA) ------------------
#define BM 128
#define BK 32
__global__ void __launch_bounds__(256, 2)
k_gemm(const float* __restrict__ x, const float* __restrict__ W) {
    __shared__ float Xs[BK][BM];   // transposed x tile: Xs[k][row]
    __shared__ float Ws[BK][DD];   // Ws[k][col]

    const int r = blockIdx.y;
    const int row0 = blockIdx.x * BM;
    const int tid = threadIdx.x;
    const int tx = tid & 15;       // col group (8 cols each)
    const int ty = tid >> 4;       // row group (8 rows each)
    const float* Wr = W + (size_t)r * DD * DD;

    unsigned long long acc[4][8];  // [row-pair][col]; pair = rows (2p, 2p+1)
#pragma unroll
    for (int p = 0; p < 4; p++)
#pragma unroll
        for (int j = 0; j < 8; j++) acc[p][j] = 0ULL;

    const int lrow = tid >> 1;           // 0..127
    const int lk = (tid & 1) * 16;       // 0 or 16

    for (int k0 = 0; k0 < DD; k0 += BK) {
        // load x tile, transposed into Xs
        const int grow = row0 + lrow;
#pragma unroll
        for (int q = 0; q < 4; q++) {
            int kk = lk + q * 4;
            float4 v = make_float4(0.f, 0.f, 0.f, 0.f);
            if (grow < NN) v = *(const float4*)&x[(size_t)grow * DD + k0 + kk];
            Xs[kk + 0][lrow] = v.x;
            Xs[kk + 1][lrow] = v.y;
            Xs[kk + 2][lrow] = v.z;
            Xs[kk + 3][lrow] = v.w;
        }
        // load W tile (linear copy, coalesced)
#pragma unroll
        for (int q = 0; q < 4; q++) {
            int lin = q * 1024 + tid * 4;
            *(float4*)&Ws[0][lin] = *(const float4*)&Wr[(size_t)k0 * DD + lin];
        }
        __syncthreads();

#pragma unroll 4
        for (int kk = 0; kk < BK; kk++) {
            ulonglong2 a01 = *(const ulonglong2*)&Xs[kk][ty * 8];
            ulonglong2 a23 = *(const ulonglong2*)&Xs[kk][ty * 8 + 4];
            unsigned long long av[4] = {a01.x, a01.y, a23.x, a23.y};
            float4 b0 = *(const float4*)&Ws[kk][tx * 8];
            float4 b1 = *(const float4*)&Ws[kk][tx * 8 + 4];
            float bv[8] = {b0.x, b0.y, b0.z, b0.w, b1.x, b1.y, b1.z, b1.w};
#pragma unroll
            for (int j = 0; j < 8; j++) {
                unsigned long long bb;
                PACK_DUP(bb, bv[j]);
#pragma unroll
                for (int p = 0; p < 4; p++) FMA2(acc[p][j], av[p], bb, acc[p][j]);
            }
        }
        __syncthreads();
    }

    // epilogue: unpack row pairs and store h
#pragma unroll
    for (int p = 0; p < 4; p++) {
        int grow = row0 + ty * 8 + 2 * p;
        float lo[8], hi[8];
#pragma unroll
        for (int j = 0; j < 8; j++) {
            float2 v = *(float2*)&acc[p][j];
            lo[j] = v.x;
            hi[j] = v.y;
        }
        size_t base = ((size_t)r * NN + grow) * DD + tx * 8;
        if (grow < NN) {
            *(float4*)&g_h[base]     = make_float4(lo[0], lo[1], lo[2], lo[3]);
            *(float4*)&g_h[base + 4] = make_float4(lo[4], lo[5], lo[6], lo[7]);
        }
        if (grow + 1 < NN) {
            *(float4*)&g_h[base + DD]     = make_float4(hi[0], hi[1], hi[2], hi[3]);
            *(float4*)&g_h[base + DD + 4] = make_float4(hi[4], hi[5], hi[6], hi[7]);
        }
    }
}

// ---------------- K3: per-node attention logits (warp per (r, n)) --------------
__global__ void k_alpha(const float* __restrict__ att_src,
                        const float* __restrict__ att_dst) {
    int wid = (blockIdx.x * blockDim.x + threadIdx.x) >> 5;
    int lane = threadIdx.x & 31;
    if (wid >= RR * NN) return;
    int r = wid / NN, n = wid - r * NN;

    float4 h4 = *(const float4*)&g_h[((size_t)r * NN + n) * DD + lane * 4];
    float4 s4 = *(const float4*)&att_src[r * DD + lane * 4];
    float4 d4 = *(const float4*)&att_dst[r * DD + lane * 4];
    float ps = h4.x * s4.x + h4.y * s4.y + h4.z * s4.z + h4.w * s4.w;
    float pd = h4.x * d4.x + h4.y * d4.y + h4.z * d4.z + h4.w * d4.w;
#pragma unroll
    for (int o = 4; o >= 1; o >>= 1) {
        ps += __shfl_xor_sync(0xffffffffu, ps, o);
        pd += __shfl_xor_sync(0xffffffffu, pd, o);
    }
    if ((lane & 7) == 0) {
        int head = lane >> 3;
        g_asrc[(r * NN + n) * HH + head] = ps;
        g_adst[(r * NN + n) * HH + head] = pd;
    }
}

// ---------------- K4: softmax denominators (thread per edge) -------------------
__global__ void k_denom(const int* __restrict__ ei) {
    int e = blockIdx.x * blockDim.x + threadIdx.x;
    int r = blockIdx.y;
    if (e >= EE) return;
    int src = __ldg(&ei[r * 2 * EE + e]);
    int dst = __ldg(&ei[r * 2 * EE + EE + e]);
    float4 a = *(const float4*)&g_asrc[(r * NN + src) * HH];
    float4 b = *(const float4*)&g_adst[(r * NN + dst) * HH];
    float v0 = a.x + b.x, v1 = a.y + b.y, v2 = a.z + b.z, v3 = a.w + b.w;
    v0 = v0 >= 0.f ? v0 : 0.2f * v0;
    v1 = v1 >= 0.f ? v1 : 0.2f * v1;
    v2 = v2 >= 0.f ? v2 : 0.2f * v2;
    v3 = v3 >= 0.f ? v3 : 0.2f * v3;
    float w0 = expf(v0), w1 = expf(v1), w2 = expf(v2), w3 = expf(v3);
    float* p = &g_denom[(r * NN + dst) * HH];
    asm volatile("red.global.add.v4.f32 [%0], {%1,%2,%3,%4};"
                 :: "l"(p), "f"(w0), "f"(w1), "f"(w2), "f"(w3) : "memory");
}

// ---------------- K5: weighted aggregation (warp per edge) ---------------------
__global__ void k_agg(const int* __restrict__ ei) {
    int w_in = threadIdx.x >> 5;
    int lane = threadIdx.x & 31;
    int e = blockIdx.x * 8 + w_in;   // blockDim.x == 256 -> 8 warps
    int r = blockIdx.y;
    if (e >= EE) return;
    int src = __ldg(&ei[r * 2 * EE + e]);
    int dst = __ldg(&ei[r * 2 * EE + EE + e]);
    int head = lane >> 3;

    float av = g_asrc[(r * NN + src) * HH + head];
    float bv = g_adst[(r * NN + dst) * HH + head];
    float dv = g_denom[(r * NN + dst) * HH + head];
    float v = av + bv;
    v = v >= 0.f ? v : 0.2f * v;
    float w = expf(v);
    float coef = g_gw[r] * (w / (dv + 1e-16f));

    float4 h4 = *(const float4*)&g_h[((size_t)r * NN + src) * DD + lane * 4];
    float* op = &g_acc[(size_t)dst * DD + lane * 4];
    asm volatile("red.global.add.v4.f32 [%0], {%1,%2,%3,%4};"
                 :: "l"(op), "f"(coef * h4.x), "f"(coef * h4.y),
                    "f"(coef * h4.z), "f"(coef * h4.w) : "memory");
}

// ---------------- K6: LayerNorm + output (warp per node) -----------------------
__global__ void k_ln(const float* __restrict__ gamma,
                     const float* __restrict__ beta,
                     float* __restrict__ out) {
    int wid = (blockIdx.x * blockDim.x + threadIdx.x) >> 5;
    int lane = threadIdx.x & 31;
    if (wid >= NN) return;
    float4 v = *(const float4*)&g_acc[(size_t)wid * DD + lane * 4];
    float s = v.x + v.y + v.z + v.w;
    float q = v.x * v.x + v.y * v.y + v.z * v.z + v.w * v.w;
#pragma unroll
    for (int o = 16; o >= 1; o >>= 1) {
        s += __shfl_xor_sync(0xffffffffu, s, o);
        q += __shfl_xor_sync(0xffffffffu, q, o);
    }
    float mu = s * (1.f / DD);
    float var = q * (1.f / DD) - mu * mu;
    float rstd = rsqrtf(var + 1e-5f);
    float4 g = *(const float4*)&gamma[lane * 4];
    float4 b = *(const float4*)&beta[lane * 4];
    float4 o4;
    o4.x = (v.x - mu) * rstd * g.x + b.x;
    o4.y = (v.y - mu) * rstd * g.y + b.y;
    o4.z = (v.z - mu) * rstd * g.z + b.z;
    o4.w = (v.w - mu) * rstd * g.w + b.w;
    *(float4*)&out[(size_t)wid * DD + lane * 4] = o4;
}

// ---------------- launch --------------------------------------------------------
extern "C" void kernel_launch(void* const* d_in, const int* in_sizes, int n_in,
                              void* d_out, int out_size) {
    const float* x       = (const float*)d_in[0];
    const int*   ei      = (const int*)d_in[1];
    // d_in[2] = edge_attr (unused by GATConv)
    const float* W       = (const float*)d_in[3];
    const float* att_src = (const float*)d_in[4];
    const float* att_dst = (const float*)d_in[5];
    const float* bias    = (const float*)d_in[6];
    const float* gate    = (const float*)d_in[7];
    const float* gamma   = (const float*)d_in[8];
    const float* beta    = (const float*)d_in[9];
    float* out = (float*)d_out;

    // K0: gate softmax + fused bias (+ write gw to tail of output)
    k_prep<<<1, DD>>>(gate, bias, out + (out_size - RR));

    // K1: init accumulator and zero denominators
    int tot = NN * DD / 4 + RR * NN * HH / 4;
    k_init<<<(tot + 255) / 256, 256>>>(x);

    // K2: GEMMs
    dim3 gg((NN + BM - 1) / BM, RR);
    k_gemm<<<gg, 256>>>(x, W);

    // K3: per-node attention logits
    k_alpha<<<(RR * NN * 32 + 255) / 256, 256>>>(att_src, att_dst);

    // K4: softmax denominators
    dim3 gd((EE + 255) / 256, RR);
    k_denom<<<gd, 256>>>(ei);

    // K5: aggregation into fused accumulator
    dim3 ga((EE + 7) / 8, RR);
    k_agg<<<ga, 256>>>(ei);

    // K6: LayerNorm + store
    k_ln<<<(NN * 32 + 255) / 256, 256>>>(gamma, beta, out);
}

// round 2
// speedup vs baseline: 1.6726x; 1.6726x over previous
#include <cuda_runtime.h>

#define NN 50000
#define EE 800000
#define RR 3
#define DD 128
#define HH 4
#define MSEG (RR * NN)            // 150000 segments (r, dst)
#define SCAN_BLK 1024             // items per scan block
#define NSB ((MSEG + SCAN_BLK - 1) / SCAN_BLK)   // 147 scan blocks

// ---------------- scratch (device globals; no allocation allowed) -------------
__device__ float g_h[(size_t)RR * NN * DD];     // per-relation transformed features
__device__ float g_asrc[RR * NN * HH];
__device__ float g_adst[RR * NN * HH];
__device__ float g_acc[(size_t)NN * DD];        // fused output accumulator
__device__ float g_gw[RR];
__device__ float g_biasf[DD];
__device__ int   g_cnt[MSEG];                   // per-(r,dst) in-degree
__device__ int   g_off[MSEG];                   // CSR start offsets
__device__ int   g_cur[MSEG];                   // scatter cursor (== end after scatter)
__device__ int   g_bsum[256];                   // scan block sums
__device__ int   g_esrc[RR * EE];               // CSR payload: src node ids

// ---------------- packed fp32x2 helpers ---------------------------------------
#define PACK_DUP(d, f) asm("mov.b64 %0, {%1, %2};" : "=l"(d) : "f"(f), "f"(f))
#define FMA2(d, a, b, c) \
    asm("fma.rn.f32x2 %0, %1, %2, %3;" : "=l"(d) : "l"(a), "l"(b), "l"(c))

// ---------------- K0: gate softmax + fused bias --------------------------------
__global__ void k_prep(const float* __restrict__ gate,
                       const float* __restrict__ bias,
                       float* __restrict__ out_gw) {
    __shared__ float gw[RR];
    int d = threadIdx.x;  // 128 threads
    if (d == 0) {
        float m = gate[0];
        for (int r = 1; r < RR; r++) m = fmaxf(m, gate[r]);
        float e[RR], s = 0.f;
        for (int r = 0; r < RR; r++) { e[r] = expf(gate[r] - m); s += e[r]; }
        for (int r = 0; r < RR; r++) {
            gw[r] = e[r] / s;
            g_gw[r] = gw[r];
            out_gw[r] = gw[r];
        }
    }
    __syncthreads();
    float b = 0.f;
    for (int r = 0; r < RR; r++) b += gw[r] * bias[r * DD + d];
    g_biasf[d] = b;
}

// ---------------- K1: init acc = x + fused_bias ; zero degree counts -----------
__global__ void k_init(const float* __restrict__ x) {
    int i = blockIdx.x * blockDim.x + threadIdx.x;
    const int ACC4 = NN * DD / 4;            // 1,600,000
    const int CNT4 = MSEG / 4;               // 37,500
    if (i < ACC4) {
        float4 xv = ((const float4*)x)[i];
        int d4 = (i & 31) * 4;               // DD/4 == 32
        float4 bf = *(const float4*)&g_biasf[d4];
        float4 o;
        o.x = xv.x + bf.x; o.y = xv.y + bf.y;
        o.z = xv.z + bf.z; o.w = xv.w + bf.w;
        ((float4*)g_acc)[i] = o;
    } else {
        int j = i - ACC4;
        if (j < CNT4) ((int4*)g_cnt)[j] = make_int4(0, 0, 0, 0);
    }
}

// ---------------- K2: GEMM h_r = x @ W_r  (fp32x2 packed FFMA) ------------------
#define BM 128
#define BK 32
__global__ void __launch_bounds__(256, 2)
k_gemm(const float* __restrict__ x, const float* __restrict__ W) {
    __shared__ float Xs[BK][BM];   // transposed x tile: Xs[k][row]
    __shared__ float Ws[BK][DD];   // Ws[k][col]

    const int r = blockIdx.y;
    const int row0 = blockIdx.x * BM;
    const int tid = threadIdx.x;
    const int tx = tid & 15;       // col group (8 cols each)
    const int ty = tid >> 4;       // row group (8 rows each)
    const float* Wr = W + (size_t)r * DD * DD;

    unsigned long long acc[4][8];  // [row-pair][col]; pair = rows (2p, 2p+1)
#pragma unroll
    for (int p = 0; p < 4; p++)
#pragma unroll
        for (int j = 0; j < 8; j++) acc[p][j] = 0ULL;

    const int lrow = tid >> 1;           // 0..127
    const int lk = (tid & 1) * 16;       // 0 or 16

    for (int k0 = 0; k0 < DD; k0 += BK) {
        const int grow = row0 + lrow;
#pragma unroll
        for (int q = 0; q < 4; q++) {
            int kk = lk + q * 4;
            float4 v = make_float4(0.f, 0.f, 0.f, 0.f);
            if (grow < NN) v = *(const float4*)&x[(size_t)grow * DD + k0 + kk];
            Xs[kk + 0][lrow] = v.x;
            Xs[kk + 1][lrow] = v.y;
            Xs[kk + 2][lrow] = v.z;
            Xs[kk + 3][lrow] = v.w;
        }
#pragma unroll
        for (int q = 0; q < 4; q++) {
            int lin = q * 1024 + tid * 4;
            *(float4*)&Ws[0][lin] = *(const float4*)&Wr[(size_t)k0 * DD + lin];
        }
        __syncthreads();

#pragma unroll 4
        for (int kk = 0; kk < BK; kk++) {
            ulonglong2 a01 = *(const ulonglong2*)&Xs[kk][ty * 8];
            ulonglong2 a23 = *(const ulonglong2*)&Xs[kk][ty * 8 + 4];
            unsigned long long av[4] = {a01.x, a01.y, a23.x, a23.y};
            float4 b0 = *(const float4*)&Ws[kk][tx * 8];
            float4 b1 = *(const float4*)&Ws[kk][tx * 8 + 4];
            float bv[8] = {b0.x, b0.y, b0.z, b0.w, b1.x, b1.y, b1.z, b1.w};
#pragma unroll
            for (int j = 0; j < 8; j++) {
                unsigned long long bb;
                PACK_DUP(bb, bv[j]);
#pragma unroll
                for (int p = 0; p < 4; p++) FMA2(acc[p][j], av[p], bb, acc[p][j]);
            }
        }
        __syncthreads();
    }

#pragma unroll
    for (int p = 0; p < 4; p++) {
        int grow = row0 + ty * 8 + 2 * p;
        float lo[8], hi[8];
#pragma unroll
        for (int j = 0; j < 8; j++) {
            float2 v = *(float2*)&acc[p][j];
            lo[j] = v.x;
            hi[j] = v.y;
        }
        size_t base = ((size_t)r * NN + grow) * DD + tx * 8;
        if (grow < NN) {
            *(float4*)&g_h[base]     = make_float4(lo[0], lo[1], lo[2], lo[3]);
            *(float4*)&g_h[base + 4] = make_float4(lo[4], lo[5], lo[6], lo[7]);
        }
        if (grow + 1 < NN) {
            *(float4*)&g_h[base + DD]     = make_float4(hi[0], hi[1], hi[2], hi[3]);
            *(float4*)&g_h[base + DD + 4] = make_float4(hi[4], hi[5], hi[6], hi[7]);
        }
    }
}

// ---------------- K3: per-node attention logits (warp per (r, n)) --------------
__global__ void k_alpha(const float* __restrict__ att_src,
                        const float* __restrict__ att_dst) {
    int wid = (blockIdx.x * blockDim.x + threadIdx.x) >> 5;
    int lane = threadIdx.x & 31;
    if (wid >= RR * NN) return;
    int r = wid / NN, n = wid - r * NN;

    float4 h4 = *(const float4*)&g_h[((size_t)r * NN + n) * DD + lane * 4];
    float4 s4 = *(const float4*)&att_src[r * DD + lane * 4];
    float4 d4 = *(const float4*)&att_dst[r * DD + lane * 4];
    float ps = h4.x * s4.x + h4.y * s4.y + h4.z * s4.z + h4.w * s4.w;
    float pd = h4.x * d4.x + h4.y * d4.y + h4.z * d4.z + h4.w * d4.w;
#pragma unroll
    for (int o = 4; o >= 1; o >>= 1) {
        ps += __shfl_xor_sync(0xffffffffu, ps, o);
        pd += __shfl_xor_sync(0xffffffffu, pd, o);
    }
    if ((lane & 7) == 0) {
        int head = lane >> 3;
        g_asrc[(r * NN + n) * HH + head] = ps;
        g_adst[(r * NN + n) * HH + head] = pd;
    }
}

// ---------------- K4a: degree histogram -----------------------------------------
__global__ void k_hist(const int* __restrict__ ei) {
    int e = blockIdx.x * blockDim.x + threadIdx.x;
    int r = blockIdx.y;
    if (e >= EE) return;
    int dst = __ldg(&ei[r * 2 * EE + EE + e]);
    atomicAdd(&g_cnt[r * NN + dst], 1);
}

// ---------------- K4b: scan stage 1 — per-block sums -----------------------------
__global__ void k_scan_a() {
    __shared__ int ws[8];
    int tid = threadIdx.x;                 // 256 threads
    int base = blockIdx.x * SCAN_BLK + tid * 4;
    int s = 0;
#pragma unroll
    for (int k = 0; k < 4; k++) {
        int idx = base + k;
        if (idx < MSEG) s += g_cnt[idx];
    }
#pragma unroll
    for (int o = 16; o >= 1; o >>= 1) s += __shfl_xor_sync(0xffffffffu, s, o);
    if ((tid & 31) == 0) ws[tid >> 5] = s;
    __syncthreads();
    if (tid == 0) {
        int t = 0;
        for (int i = 0; i < 8; i++) t += ws[i];
        g_bsum[blockIdx.x] = t;
    }
}

// ---------------- K4c: scan stage 2 — scan of block sums (single block) ----------
__global__ void k_scan_b() {
    if (threadIdx.x == 0) {
        int run = 0;
        for (int i = 0; i < NSB; i++) {
            int v = g_bsum[i];
            g_bsum[i] = run;
            run += v;
        }
    }
}

// ---------------- K4d: scan stage 3 — exclusive offsets + cursor init ------------
__global__ void k_scan_c() {
    __shared__ int ws[8];
    int tid = threadIdx.x;
    int lane = tid & 31, warp = tid >> 5;
    int base = blockIdx.x * SCAN_BLK + tid * 4;
    int c[4];
#pragma unroll
    for (int k = 0; k < 4; k++) {
        int idx = base + k;
        c[k] = (idx < MSEG) ? g_cnt[idx] : 0;
    }
    int t = c[0] + c[1] + c[2] + c[3];
    int inc = t;
#pragma unroll
    for (int o = 1; o < 32; o <<= 1) {
        int v = __shfl_up_sync(0xffffffffu, inc, o);
        if (lane >= o) inc += v;
    }
    if (lane == 31) ws[warp] = inc;
    __syncthreads();
    if (tid == 0) {
        int run = 0;
        for (int i = 0; i < 8; i++) { int v = ws[i]; ws[i] = run; run += v; }
    }
    __syncthreads();
    int ex = inc - t + ws[warp] + g_bsum[blockIdx.x];
#pragma unroll
    for (int k = 0; k < 4; k++) {
        int idx = base + k;
        if (idx < MSEG) { g_off[idx] = ex; g_cur[idx] = ex; }
        ex += c[k];
    }
}

// ---------------- K4e: scatter edges into CSR ------------------------------------
__global__ void k_scatter(const int* __restrict__ ei) {
    int e = blockIdx.x * blockDim.x + threadIdx.x;
    int r = blockIdx.y;
    if (e >= EE) return;
    int src = __ldg(&ei[r * 2 * EE + e]);
    int dst = __ldg(&ei[r * 2 * EE + EE + e]);
    int pos = atomicAdd(&g_cur[r * NN + dst], 1);
    g_esrc[pos] = src;
}

// ---------------- K5: fused softmax + aggregation (warp per (r, dst)) ------------
__global__ void __launch_bounds__(256)
k_agg(int dummy) {
    int wid = (blockIdx.x * blockDim.x + threadIdx.x) >> 5;
    int lane = threadIdx.x & 31;
    if (wid >= MSEG) return;
    int r = wid / NN, n = wid - r * NN;
    int head = lane >> 3;
    int c4 = lane * 4;

    int beg = g_off[wid];
    int end = g_cur[wid];                 // == beg + count after scatter
    if (beg == end) return;               // isolated node: contributes 0

    float ad = g_adst[wid * HH + head];
    float denom = 0.f;
    float4 acc = make_float4(0.f, 0.f, 0.f, 0.f);
    const float* hr = g_h + (size_t)r * NN * DD;
    const float* ar = g_asrc + (size_t)r * NN * HH;

#pragma unroll 2
    for (int i = beg; i < end; i++) {
        int src = __ldg(&g_esrc[i]);
        float as = __ldg(&ar[src * HH + head]);
        float v = as + ad;
        v = v >= 0.f ? v : 0.2f * v;
        float w = __expf(v);
        denom += w;
        float4 h4 = *(const float4*)&hr[(size_t)src * DD + c4];
        acc.x += w * h4.x; acc.y += w * h4.y;
        acc.z += w * h4.z; acc.w += w * h4.w;
    }
    float scale = g_gw[r] / (denom + 1e-16f);
    float* op = &g_acc[(size_t)n * DD + c4];
    asm volatile("red.global.add.v4.f32 [%0], {%1,%2,%3,%4};"
                 :: "l"(op), "f"(scale * acc.x), "f"(scale * acc.y),
                    "f"(scale * acc.z), "f"(scale * acc.w) : "memory");
}

// ---------------- K6: LayerNorm + output (warp per node) -------------------------
__global__ void k_ln(const float* __restrict__ gamma,
                     const float* __restrict__ beta,
                     float* __restrict__ out) {
    int wid = (blockIdx.x * blockDim.x + threadIdx.x) >> 5;
    int lane = threadIdx.x & 31;
    if (wid >= NN) return;
    float4 v = *(const float4*)&g_acc[(size_t)wid * DD + lane * 4];
    float s = v.x + v.y + v.z + v.w;
    float q = v.x * v.x + v.y * v.y + v.z * v.z + v.w * v.w;
#pragma unroll
    for (int o = 16; o >= 1; o >>= 1) {
        s += __shfl_xor_sync(0xffffffffu, s, o);
        q += __shfl_xor_sync(0xffffffffu, q, o);
    }
    float mu = s * (1.f / DD);
    float var = q * (1.f / DD) - mu * mu;
    float rstd = rsqrtf(var + 1e-5f);
    float4 g = *(const float4*)&gamma[lane * 4];
    float4 b = *(const float4*)&beta[lane * 4];
    float4 o4;
    o4.x = (v.x - mu) * rstd * g.x + b.x;
    o4.y = (v.y - mu) * rstd * g.y + b.y;
    o4.z = (v.z - mu) * rstd * g.z + b.z;
    o4.w = (v.w - mu) * rstd * g.w + b.w;
    *(float4*)&out[(size_t)wid * DD + lane * 4] = o4;
}

// ---------------- launch ----------------------------------------------------------
extern "C" void kernel_launch(void* const* d_in, const int* in_sizes, int n_in,
                              void* d_out, int out_size) {
    const float* x       = (const float*)d_in[0];
    const int*   ei      = (const int*)d_in[1];
    // d_in[2] = edge_attr (unused by GATConv)
    const float* W       = (const float*)d_in[3];
    const float* att_src = (const float*)d_in[4];
    const float* att_dst = (const float*)d_in[5];
    const float* bias    = (const float*)d_in[6];
    const float* gate    = (const float*)d_in[7];
    const float* gamma   = (const float*)d_in[8];
    const float* beta    = (const float*)d_in[9];
    float* out = (float*)d_out;

    // K0: gate softmax + fused bias (+ write gw to tail of output)
    k_prep<<<1, DD>>>(gate, bias, out + (out_size - RR));

    // K1: init accumulator (x + bias) and zero degree counts
    int tot = NN * DD / 4 + MSEG / 4;
    k_init<<<(tot + 255) / 256, 256>>>(x);

    // K2: GEMMs
    dim3 gg((NN + BM - 1) / BM, RR);
    k_gemm<<<gg, 256>>>(x, W);

    // K3: per-node attention logits
    k_alpha<<<(RR * NN * 32 + 255) / 256, 256>>>(att_src, att_dst);

    // K4: CSR build — histogram, scan, scatter
    dim3 gh((EE + 511) / 512, RR);
    k_hist<<<gh, 512>>>(ei);
    k_scan_a<<<NSB, 256>>>();
    k_scan_b<<<1, 32>>>();
    k_scan_c<<<NSB, 256>>>();
    k_scatter<<<gh, 512>>>(ei);

    // K5: fused softmax + aggregation, one pass, one red per (r,dst)
    k_agg<<<(MSEG * 32 + 255) / 256, 256>>>(0);

    // K6: LayerNorm + store
    k_ln<<<(NN * 32 + 255) / 256, 256>>>(gamma, beta, out);
}

// round 4
// speedup vs baseline: 1.8273x; 1.0925x over previous
#include <cuda_runtime.h>
#include <cuda_fp16.h>
#include <cstdint>

#define NN 50000
#define EE 800000
#define RR 3
#define DD 128
#define HH 4
#define MSEG (RR * NN)            // 150000 segments (r, dst)
#define SCAN_BLK 1024
#define NSB ((MSEG + SCAN_BLK - 1) / SCAN_BLK)   // 147

// ---------------- scratch (device globals; no allocation allowed) -------------
__device__ __align__(16) __half g_hh[(size_t)RR * NN * DD]; // fp16 features (gather copy)
__device__ float g_asrc[RR * NN * HH];
__device__ float g_adst[RR * NN * HH];
__device__ float g_acc[(size_t)NN * DD];        // fused output accumulator
__device__ float g_gw[RR];
__device__ float g_biasf[DD];
__device__ int   g_cnt[MSEG];
__device__ int   g_off[MSEG];
__device__ int   g_cur[MSEG];
__device__ int   g_bsum[256];
__device__ int   g_esrc[RR * EE];

// ---------------- packed fp32x2 helpers ---------------------------------------
#define PACK_DUP(d, f) asm("mov.b64 %0, {%1, %2};" : "=l"(d) : "f"(f), "f"(f))
#define FMA2(d, a, b, c) \
    asm("fma.rn.f32x2 %0, %1, %2, %3;" : "=l"(d) : "l"(a), "l"(b), "l"(c))

// ---------------- K0: gate softmax + fused bias --------------------------------
__global__ void k_prep(const float* __restrict__ gate,
                       const float* __restrict__ bias,
                       float* __restrict__ out_gw) {
    __shared__ float gw[RR];
    int d = threadIdx.x;  // 128
    if (d == 0) {
        float m = gate[0];
        for (int r = 1; r < RR; r++) m = fmaxf(m, gate[r]);
        float e[RR], s = 0.f;
        for (int r = 0; r < RR; r++) { e[r] = expf(gate[r] - m); s += e[r]; }
        for (int r = 0; r < RR; r++) {
            gw[r] = e[r] / s;
            g_gw[r] = gw[r];
            out_gw[r] = gw[r];
        }
    }
    __syncthreads();
    float b = 0.f;
    for (int r = 0; r < RR; r++) b += gw[r] * bias[r * DD + d];
    g_biasf[d] = b;
}

// ---------------- K1: init acc = x + fused_bias ; zero degree counts -----------
__global__ void k_init(const float* __restrict__ x) {
    int i = blockIdx.x * blockDim.x + threadIdx.x;
    const int ACC4 = NN * DD / 4;
    const int CNT4 = MSEG / 4;
    if (i < ACC4) {
        float4 xv = ((const float4*)x)[i];
        int d4 = (i & 31) * 4;
        float4 bf = *(const float4*)&g_biasf[d4];
        float4 o;
        o.x = xv.x + bf.x; o.y = xv.y + bf.y;
        o.z = xv.z + bf.z; o.w = xv.w + bf.w;
        ((float4*)g_acc)[i] = o;
    } else {
        int j = i - ACC4;
        if (j < CNT4) ((int4*)g_cnt)[j] = make_int4(0, 0, 0, 0);
    }
}

// ---------------- K2: GEMM h_r = x @ W_r  (fp32x2) + fused alpha epilogue -------
#define BM 128
#define BK 32
__global__ void __launch_bounds__(256, 2)
k_gemm(const float* __restrict__ x, const float* __restrict__ W,
       const float* __restrict__ att_src, const float* __restrict__ att_dst) {
    __shared__ float Xs[BK][BM];   // transposed x tile: Xs[k][row]
    __shared__ float Ws[BK][DD];   // Ws[k][col]
    __shared__ float as_s[DD], ad_s[DD];

    const int r = blockIdx.y;
    const int row0 = blockIdx.x * BM;
    const int tid = threadIdx.x;
    const int tx = tid & 15;       // col group (8 cols each)
    const int ty = tid >> 4;       // row group (8 rows each)
    const float* Wr = W + (size_t)r * DD * DD;

    if (tid < DD) {
        as_s[tid] = __ldg(&att_src[r * DD + tid]);
        ad_s[tid] = __ldg(&att_dst[r * DD + tid]);
    }

    unsigned long long acc[4][8];  // [row-pair][col]; pair = rows (2p, 2p+1)
#pragma unroll
    for (int p = 0; p < 4; p++)
#pragma unroll
        for (int j = 0; j < 8; j++) acc[p][j] = 0ULL;

    const int lrow = tid >> 1;           // 0..127
    const int lk = (tid & 1) * 16;       // 0 or 16

    for (int k0 = 0; k0 < DD; k0 += BK) {
        const int grow = row0 + lrow;
#pragma unroll
        for (int q = 0; q < 4; q++) {
            int kk = lk + q * 4;
            float4 v = make_float4(0.f, 0.f, 0.f, 0.f);
            if (grow < NN) v = *(const float4*)&x[(size_t)grow * DD + k0 + kk];
            Xs[kk + 0][lrow] = v.x;
            Xs[kk + 1][lrow] = v.y;
            Xs[kk + 2][lrow] = v.z;
            Xs[kk + 3][lrow] = v.w;
        }
#pragma unroll
        for (int q = 0; q < 4; q++) {
            int lin = q * 1024 + tid * 4;
            *(float4*)&Ws[0][lin] = *(const float4*)&Wr[(size_t)k0 * DD + lin];
        }
        __syncthreads();

#pragma unroll 4
        for (int kk = 0; kk < BK; kk++) {
            ulonglong2 a01 = *(const ulonglong2*)&Xs[kk][ty * 8];
            ulonglong2 a23 = *(const ulonglong2*)&Xs[kk][ty * 8 + 4];
            unsigned long long av[4] = {a01.x, a01.y, a23.x, a23.y};
            float4 b0 = *(const float4*)&Ws[kk][tx * 8];
            float4 b1 = *(const float4*)&Ws[kk][tx * 8 + 4];
            float bv[8] = {b0.x, b0.y, b0.z, b0.w, b1.x, b1.y, b1.z, b1.w};
#pragma unroll
            for (int j = 0; j < 8; j++) {
                unsigned long long bb;
                PACK_DUP(bb, bv[j]);
#pragma unroll
                for (int p = 0; p < 4; p++) FMA2(acc[p][j], av[p], bb, acc[p][j]);
            }
        }
        __syncthreads();
    }

    // ---- epilogue: fp16 store + fused attention-logit dots --------------------
    // this thread's 8 cols (tx*8..tx*8+7) lie inside head (tx>>2); lanes with
    // the same ty and tx in {4h..4h+3} are 4 consecutive lanes -> shfl reduce.
    const int head = tx >> 2;
    float asv[8], adv[8];
#pragma unroll
    for (int j = 0; j < 8; j++) {
        asv[j] = as_s[tx * 8 + j];
        adv[j] = ad_s[tx * 8 + j];
    }

#pragma unroll
    for (int p = 0; p < 4; p++) {
        int grow = row0 + ty * 8 + 2 * p;
        float lo[8], hi[8];
#pragma unroll
        for (int j = 0; j < 8; j++) {
            float2 v = *(float2*)&acc[p][j];
            lo[j] = v.x;
            hi[j] = v.y;
        }
        float psl = 0.f, pdl = 0.f, psh = 0.f, pdh = 0.f;
#pragma unroll
        for (int j = 0; j < 8; j++) {
            psl += lo[j] * asv[j];  pdl += lo[j] * adv[j];
            psh += hi[j] * asv[j];  pdh += hi[j] * adv[j];
        }
#pragma unroll
        for (int o = 1; o <= 2; o <<= 1) {
            psl += __shfl_xor_sync(0xffffffffu, psl, o);
            pdl += __shfl_xor_sync(0xffffffffu, pdl, o);
            psh += __shfl_xor_sync(0xffffffffu, psh, o);
            pdh += __shfl_xor_sync(0xffffffffu, pdh, o);
        }

        __half2 ol[4], oh[4];
#pragma unroll
        for (int j = 0; j < 4; j++) {
            ol[j] = __floats2half2_rn(lo[2 * j], lo[2 * j + 1]);
            oh[j] = __floats2half2_rn(hi[2 * j], hi[2 * j + 1]);
        }
        size_t base = ((size_t)r * NN + grow) * DD + tx * 8;
        if (grow < NN) {
            *(uint4*)&g_hh[base] = *(uint4*)ol;
            if ((tx & 3) == 0) {
                g_asrc[((size_t)r * NN + grow) * HH + head] = psl;
                g_adst[((size_t)r * NN + grow) * HH + head] = pdl;
            }
        }
        if (grow + 1 < NN) {
            *(uint4*)&g_hh[base + DD] = *(uint4*)oh;
            if ((tx & 3) == 0) {
                g_asrc[((size_t)r * NN + grow + 1) * HH + head] = psh;
                g_adst[((size_t)r * NN + grow + 1) * HH + head] = pdh;
            }
        }
    }
}

// ---------------- K4a: degree histogram -----------------------------------------
__global__ void k_hist(const int* __restrict__ ei) {
    int e = blockIdx.x * blockDim.x + threadIdx.x;
    int r = blockIdx.y;
    if (e >= EE) return;
    int dst = __ldg(&ei[r * 2 * EE + EE + e]);
    atomicAdd(&g_cnt[r * NN + dst], 1);
}

// ---------------- K4b/c/d: scan -------------------------------------------------
__global__ void k_scan_a() {
    __shared__ int ws[8];
    int tid = threadIdx.x;
    int base = blockIdx.x * SCAN_BLK + tid * 4;
    int s = 0;
#pragma unroll
    for (int k = 0; k < 4; k++) {
        int idx = base + k;
        if (idx < MSEG) s += g_cnt[idx];
    }
#pragma unroll
    for (int o = 16; o >= 1; o >>= 1) s += __shfl_xor_sync(0xffffffffu, s, o);
    if ((tid & 31) == 0) ws[tid >> 5] = s;
    __syncthreads();
    if (tid == 0) {
        int t = 0;
        for (int i = 0; i < 8; i++) t += ws[i];
        g_bsum[blockIdx.x] = t;
    }
}
__global__ void k_scan_b() {
    if (threadIdx.x == 0) {
        int run = 0;
        for (int i = 0; i < NSB; i++) { int v = g_bsum[i]; g_bsum[i] = run; run += v; }
    }
}
__global__ void k_scan_c() {
    __shared__ int ws[8];
    int tid = threadIdx.x;
    int lane = tid & 31, warp = tid >> 5;
    int base = blockIdx.x * SCAN_BLK + tid * 4;
    int c[4];
#pragma unroll
    for (int k = 0; k < 4; k++) {
        int idx = base + k;
        c[k] = (idx < MSEG) ? g_cnt[idx] : 0;
    }
    int t = c[0] + c[1] + c[2] + c[3];
    int inc = t;
#pragma unroll
    for (int o = 1; o < 32; o <<= 1) {
        int v = __shfl_up_sync(0xffffffffu, inc, o);
        if (lane >= o) inc += v;
    }
    if (lane == 31) ws[warp] = inc;
    __syncthreads();
    if (tid == 0) {
        int run = 0;
        for (int i = 0; i < 8; i++) { int v = ws[i]; ws[i] = run; run += v; }
    }
    __syncthreads();
    int ex = inc - t + ws[warp] + g_bsum[blockIdx.x];
#pragma unroll
    for (int k = 0; k < 4; k++) {
        int idx = base + k;
        if (idx < MSEG) { g_off[idx] = ex; g_cur[idx] = ex; }
        ex += c[k];
    }
}

// ---------------- K4e: scatter edges into CSR ------------------------------------
__global__ void k_scatter(const int* __restrict__ ei) {
    int e = blockIdx.x * blockDim.x + threadIdx.x;
    int r = blockIdx.y;
    if (e >= EE) return;
    int src = __ldg(&ei[r * 2 * EE + e]);
    int dst = __ldg(&ei[r * 2 * EE + EE + e]);
    int pos = atomicAdd(&g_cur[r * NN + dst], 1);
    g_esrc[pos] = src;
}

// ---------------- K5: fused softmax + aggregation (warp per (r, dst)) ------------
__global__ void __launch_bounds__(256)
k_agg(int dummy) {
    int wid = (blockIdx.x * blockDim.x + threadIdx.x) >> 5;
    int lane = threadIdx.x & 31;
    if (wid >= MSEG) return;
    int r = wid / NN, n = wid - r * NN;
    int head = lane >> 3;
    int c4 = lane * 4;

    int beg = g_off[wid];
    int end = g_cur[wid];
    if (beg == end) return;

    float adv = g_adst[wid * HH + head];
    float denom = 0.f;
    float4 acc = make_float4(0.f, 0.f, 0.f, 0.f);
    const __half* hr = g_hh + (size_t)r * NN * DD;
    const float* ar = g_asrc + (size_t)r * NN * HH;

#pragma unroll 2
    for (int i = beg; i < end; i++) {
        int src = __ldg(&g_esrc[i]);
        float asv = __ldg(&ar[src * HH + head]);
        float v = asv + adv;
        v = v >= 0.f ? v : 0.2f * v;
        float w = __expf(v);
        denom += w;
        uint2 hv = __ldg((const uint2*)&hr[(size_t)src * DD + c4]);
        float2 f0 = __half22float2(*(__half2*)&hv.x);
        float2 f1 = __half22float2(*(__half2*)&hv.y);
        acc.x += w * f0.x; acc.y += w * f0.y;
        acc.z += w * f1.x; acc.w += w * f1.y;
    }
    float scale = g_gw[r] / (denom + 1e-16f);
    float* op = &g_acc[(size_t)n * DD + c4];
    asm volatile("red.global.add.v4.f32 [%0], {%1,%2,%3,%4};"
                 :: "l"(op), "f"(scale * acc.x), "f"(scale * acc.y),
                    "f"(scale * acc.z), "f"(scale * acc.w) : "memory");
}

// ---------------- K6: LayerNorm + output (warp per node) -------------------------
__global__ void k_ln(const float* __restrict__ gamma,
                     const float* __restrict__ beta,
                     float* __restrict__ out) {
    int wid = (blockIdx.x * blockDim.x + threadIdx.x) >> 5;
    int lane = threadIdx.x & 31;
    if (wid >= NN) return;
    float4 v = *(const float4*)&g_acc[(size_t)wid * DD + lane * 4];
    float s = v.x + v.y + v.z + v.w;
    float q = v.x * v.x + v.y * v.y + v.z * v.z + v.w * v.w;
#pragma unroll
    for (int o = 16; o >= 1; o >>= 1) {
        s += __shfl_xor_sync(0xffffffffu, s, o);
        q += __shfl_xor_sync(0xffffffffu, q, o);
    }
    float mu = s * (1.f / DD);
    float var = q * (1.f / DD) - mu * mu;
    float rstd = rsqrtf(var + 1e-5f);
    float4 g = *(const float4*)&gamma[lane * 4];
    float4 b = *(const float4*)&beta[lane * 4];
    float4 o4;
    o4.x = (v.x - mu) * rstd * g.x + b.x;
    o4.y = (v.y - mu) * rstd * g.y + b.y;
    o4.z = (v.z - mu) * rstd * g.z + b.z;
    o4.w = (v.w - mu) * rstd * g.w + b.w;
    *(float4*)&out[(size_t)wid * DD + lane * 4] = o4;
}

// ---------------- launch ----------------------------------------------------------
extern "C" void kernel_launch(void* const* d_in, const int* in_sizes, int n_in,
                              void* d_out, int out_size) {
    const float* x       = (const float*)d_in[0];
    const int*   ei      = (const int*)d_in[1];
    const float* W       = (const float*)d_in[3];
    const float* att_src = (const float*)d_in[4];
    const float* att_dst = (const float*)d_in[5];
    const float* bias    = (const float*)d_in[6];
    const float* gate    = (const float*)d_in[7];
    const float* gamma   = (const float*)d_in[8];
    const float* beta    = (const float*)d_in[9];
    float* out = (float*)d_out;

    k_prep<<<1, DD>>>(gate, bias, out + (out_size - RR));

    int tot = NN * DD / 4 + MSEG / 4;
    k_init<<<(tot + 255) / 256, 256>>>(x);

    dim3 gg((NN + BM - 1) / BM, RR);
    k_gemm<<<gg, 256>>>(x, W, att_src, att_dst);

    dim3 gh((EE + 511) / 512, RR);
    k_hist<<<gh, 512>>>(ei);
    k_scan_a<<<NSB, 256>>>();
    k_scan_b<<<1, 32>>>();
    k_scan_c<<<NSB, 256>>>();
    k_scatter<<<gh, 512>>>(ei);

    k_agg<<<(MSEG * 32 + 255) / 256, 256>>>(0);

    k_ln<<<(NN * 32 + 255) / 256, 256>>>(gamma, beta, out);
}